// round 1
// baseline (speedup 1.0000x reference)
#include <cuda_runtime.h>
#include <math.h>

#define NN   2048
#define DD   128
#define HH   8
#define HDIM 16
#define LL   8
#define GG   16
#define OUTD 64
#define EMAX 65536
#define EPSB 1e-5f
#define QSCALE 0.25f   // HD^-0.5 = 16^-0.5

// ---------------- scratch (device globals; no allocation) ----------------
__device__ int   g_A[NN * NN];          // dense adjacency counts (16MB)
__device__ int   g_nnz[NN];
__device__ int   g_rowptr[NN + 1];
__device__ int   g_cols[EMAX];
__device__ float g_vals[EMAX];
__device__ float g_h  [NN * DD];
__device__ float g_q  [NN * DD];
__device__ float g_k  [NN * DD];
__device__ float g_v  [NN * DD];
__device__ float g_o  [NN * DD];
__device__ float g_t1 [NN * DD];
__device__ float g_ffn[NN * 2 * DD];
__device__ float g_vtot[HH * HDIM];
__device__ float g_pooled[GG * DD];

// ---------------- adjacency build ----------------
__global__ void zero_A_kernel() {
    int t = blockIdx.x * blockDim.x + threadIdx.x;
    if (t < NN * NN) g_A[t] = 0;
}

__global__ void edge_scatter_kernel(const int* __restrict__ ei, int E) {
    int e = blockIdx.x * blockDim.x + threadIdx.x;
    if (e >= E) return;
    int src = ei[e];
    int dst = ei[E + e];
    atomicAdd(&g_A[src * NN + dst], 1);
}

__global__ void row_count_kernel() {
    int warp = (blockIdx.x * blockDim.x + threadIdx.x) >> 5;
    int lane = threadIdx.x & 31;
    if (warp >= NN) return;
    const int* arow = g_A + warp * NN;
    int cnt = 0;
    for (int m = lane; m < NN; m += 32) cnt += (arow[m] != 0);
    #pragma unroll
    for (int o = 16; o > 0; o >>= 1) cnt += __shfl_down_sync(0xffffffffu, cnt, o);
    if (lane == 0) g_nnz[warp] = cnt;
}

__global__ void scan_rows_kernel() {
    __shared__ int chunk[64];
    __shared__ int chunkoff[64];
    int t = threadIdx.x;  // 64 threads
    int s = 0;
    for (int i = 0; i < 32; i++) s += g_nnz[t * 32 + i];
    chunk[t] = s;
    __syncthreads();
    if (t == 0) {
        int run = 0;
        for (int i = 0; i < 64; i++) { chunkoff[i] = run; run += chunk[i]; }
        g_rowptr[NN] = run;
    }
    __syncthreads();
    int off = chunkoff[t];
    for (int i = 0; i < 32; i++) {
        g_rowptr[t * 32 + i] = off;
        off += g_nnz[t * 32 + i];
    }
}

__global__ void compact_rows_kernel() {
    int warp = (blockIdx.x * blockDim.x + threadIdx.x) >> 5;
    int lane = threadIdx.x & 31;
    if (warp >= NN) return;
    int row = warp;
    int pos = g_rowptr[row];
    const int* arow = g_A + row * NN;
    for (int base = 0; base < NN; base += 32) {
        int v = arow[base + lane];
        unsigned mask = __ballot_sync(0xffffffffu, v != 0);
        if (v) {
            int off = __popc(mask & ((1u << lane) - 1));
            g_cols[pos + off] = base + lane;
            g_vals[pos + off] = (float)v;
        }
        pos += __popc(mask);
    }
}

// ---------------- h init ----------------
__global__ void init_h_kernel(const float* __restrict__ X, const float* __restrict__ pos,
                              const float* __restrict__ pW, const float* __restrict__ pb,
                              const float* __restrict__ peW, const float* __restrict__ peb,
                              float* __restrict__ h) {
    int t = blockIdx.x * blockDim.x + threadIdx.x;
    if (t >= NN * DD) return;
    int n = t >> 7, d = t & 127;
    float s = pb[d] + peb[d];
    #pragma unroll
    for (int k = 0; k < 4; k++) s += X[n * 4 + k] * pW[k * DD + d];
    #pragma unroll
    for (int k = 0; k < 2; k++) s += pos[n * 2 + k] * peW[k * DD + d];
    h[t] = s;
}

// ---------------- SGEMM: C[M,N] = epi((A[M,K] @ B[K,N] + bias)*alpha) ----------------
// mode 0: C = (AB + bias) * alpha
// mode 1: C = AB + bias + Cadd
// mode 2: C = relu(AB + bias)
__global__ __launch_bounds__(256) void sgemm_kernel(
    const float* __restrict__ A, const float* __restrict__ B,
    const float* __restrict__ bias, const float* __restrict__ Cadd,
    float* __restrict__ C, int M, int N, int K, float alpha, int mode)
{
    const int BM = 64, BN = 64, BK = 16, TM = 4, TN = 4;
    __shared__ float As[BK][BM];
    __shared__ float Bs[BK][BN + 1];
    int bm = blockIdx.y * BM, bn = blockIdx.x * BN;
    int tid = threadIdx.x;
    int ty = tid / 16, tx = tid % 16;
    float acc[TM][TN] = {};
    for (int k0 = 0; k0 < K; k0 += BK) {
        for (int i = tid; i < BM * BK; i += 256) {
            int m = i / BK, k = i % BK;
            As[k][m] = A[(bm + m) * K + k0 + k];
        }
        for (int i = tid; i < BK * BN; i += 256) {
            int k = i / BN, n = i % BN;
            Bs[k][n] = B[(k0 + k) * N + bn + n];
        }
        __syncthreads();
        #pragma unroll
        for (int k = 0; k < BK; k++) {
            float a[TM], b[TN];
            #pragma unroll
            for (int i = 0; i < TM; i++) a[i] = As[k][ty * TM + i];
            #pragma unroll
            for (int j = 0; j < TN; j++) b[j] = Bs[k][tx * TN + j];
            #pragma unroll
            for (int i = 0; i < TM; i++)
                #pragma unroll
                for (int j = 0; j < TN; j++) acc[i][j] += a[i] * b[j];
        }
        __syncthreads();
    }
    #pragma unroll
    for (int i = 0; i < TM; i++) {
        int m = bm + ty * TM + i;
        #pragma unroll
        for (int j = 0; j < TN; j++) {
            int n = bn + tx * TN + j;
            float v = (acc[i][j] + bias[n]) * alpha;
            if (mode == 1) v += Cadd[m * N + n];
            if (mode == 2) v = fmaxf(v, 0.f);
            C[m * N + n] = v;
        }
    }
}

// ---------------- per-head V column sums ----------------
__global__ void vtot_kernel(const float* __restrict__ V) {
    __shared__ float sh[512];
    int head = blockIdx.x;
    int t = threadIdx.x;           // 512 threads
    int d = t & 15, g = t >> 4;    // 32 row groups x 16 dims
    const float* Vh = V + head * (NN * HDIM);
    float part = 0.f;
    for (int row = g; row < NN; row += 32) part += Vh[row * HDIM + d];
    sh[t] = part;
    __syncthreads();
    if (t < HDIM) {
        float s = 0.f;
        for (int gg = 0; gg < 32; gg++) s += sh[gg * HDIM + t];
        g_vtot[head * HDIM + t] = s;
    }
}

// ---------------- sparse multiply-mask softmax attention ----------------
// softmax over the FULL row: zero-A entries score 0, handled analytically.
__global__ __launch_bounds__(256) void attn_kernel(
    const float* __restrict__ Q, const float* __restrict__ K,
    const float* __restrict__ V, float* __restrict__ O)
{
    int t = blockIdx.x * blockDim.x + threadIdx.x;
    if (t >= HH * NN) return;
    int head = t >> 11;
    int n = t & (NN - 1);
    const float* Qh = Q + head * (NN * HDIM);
    const float* Kh = K + head * (NN * HDIM);
    const float* Vh = V + head * (NN * HDIM);

    float q[HDIM];
    #pragma unroll
    for (int d = 0; d < HDIM; d++) q[d] = Qh[n * HDIM + d];

    float mrun = 0.f;          // zero-entry score is 0 -> it's always in the max set
    float denom = 0.f;
    float acc[HDIM] = {};
    float vsum[HDIM] = {};

    int s0 = g_rowptr[n], s1 = g_rowptr[n + 1];
    for (int e = s0; e < s1; e++) {
        int m = g_cols[e];
        float a = g_vals[e];
        float dot = 0.f;
        #pragma unroll
        for (int d = 0; d < HDIM; d++) dot += q[d] * Kh[m * HDIM + d];
        float s = dot * a;
        float vreg[HDIM];
        #pragma unroll
        for (int d = 0; d < HDIM; d++) vreg[d] = Vh[m * HDIM + d];
        #pragma unroll
        for (int d = 0; d < HDIM; d++) vsum[d] += vreg[d];
        if (s > mrun) {
            float r = expf(mrun - s);
            denom *= r;
            #pragma unroll
            for (int d = 0; d < HDIM; d++) acc[d] *= r;
            mrun = s;
        }
        float ee = expf(s - mrun);
        denom += ee;
        #pragma unroll
        for (int d = 0; d < HDIM; d++) acc[d] += ee * vreg[d];
    }
    int nnz = s1 - s0;
    float e0 = expf(-mrun);
    denom += (float)(NN - nnz) * e0;
    float inv = 1.f / denom;
    #pragma unroll
    for (int d = 0; d < HDIM; d++)
        O[head * (NN * HDIM) + n * HDIM + d] =
            (acc[d] + e0 * (g_vtot[head * HDIM + d] - vsum[d])) * inv;
}

// ---------------- BatchNorm1d (training-mode, biased var over node axis) ----------------
__global__ __launch_bounds__(256) void bn_kernel(
    const float* __restrict__ x, const float* __restrict__ gamma,
    const float* __restrict__ beta, float* __restrict__ out)
{
    int c = blockIdx.x;
    int t = threadIdx.x;  // 256
    double s = 0.0, s2 = 0.0;
    for (int r = t; r < NN; r += 256) {
        float v = x[r * DD + c];
        s += v; s2 += (double)v * v;
    }
    __shared__ double sh[256], sh2[256];
    sh[t] = s; sh2[t] = s2;
    __syncthreads();
    for (int o = 128; o > 0; o >>= 1) {
        if (t < o) { sh[t] += sh[t + o]; sh2[t] += sh2[t + o]; }
        __syncthreads();
    }
    __shared__ float mean_s, inv_s;
    if (t == 0) {
        double m = sh[0] / NN;
        double var = sh2[0] / NN - m * m;
        mean_s = (float)m;
        inv_s = rsqrtf((float)var + EPSB);
    }
    __syncthreads();
    float gsc = gamma[c] * inv_s, b = beta[c], m = mean_s;
    for (int r = t; r < NN; r += 256)
        out[r * DD + c] = gsc * (x[r * DD + c] - m) + b;
}

// ---------------- pooling + final MLP ----------------
__global__ void zero_pooled_kernel() {
    int t = blockIdx.x * blockDim.x + threadIdx.x;
    if (t < GG * DD) g_pooled[t] = 0.f;
}

__global__ void pool_kernel(const int* __restrict__ gid) {
    int t = blockIdx.x * blockDim.x + threadIdx.x;
    if (t >= NN * DD) return;
    int n = t >> 7, d = t & 127;
    atomicAdd(&g_pooled[gid[n] * DD + d], g_h[t]);
}

__global__ void final_mlp_kernel(const float* __restrict__ W1, const float* __restrict__ b1,
                                 const float* __restrict__ W2, const float* __restrict__ b2,
                                 float* __restrict__ out) {
    __shared__ float p[DD], hid[DD];
    int g = blockIdx.x, t = threadIdx.x;  // 128 threads
    p[t] = g_pooled[g * DD + t];
    __syncthreads();
    float s = b1[t];
    for (int k = 0; k < DD; k++) s += p[k] * W1[k * DD + t];
    hid[t] = fmaxf(s, 0.f);
    __syncthreads();
    if (t < OUTD) {
        float s2 = b2[t];
        for (int k = 0; k < DD; k++) s2 += hid[k] * W2[k * OUTD + t];
        out[g * OUTD + t] = s2;
    }
}

// ---------------- launch ----------------
extern "C" void kernel_launch(void* const* d_in, const int* in_sizes, int n_in,
                              void* d_out, int out_size) {
    // num_graphs may or may not be materialized as a 1-element input at slot 4
    int off = (n_in > 4 && in_sizes[4] == 1) ? 1 : 0;

    const float* X     = (const float*)d_in[0];
    const float* pos   = (const float*)d_in[1];
    const int*   ei    = (const int*)  d_in[2];
    const int*   gid   = (const int*)  d_in[3];
    const float* projW = (const float*)d_in[4 + off];
    const float* projb = (const float*)d_in[5 + off];
    const float* peW   = (const float*)d_in[6 + off];
    const float* peb   = (const float*)d_in[7 + off];
    const float* Wq    = (const float*)d_in[8 + off];
    const float* bq    = (const float*)d_in[9 + off];
    const float* Wk    = (const float*)d_in[10 + off];
    const float* bk    = (const float*)d_in[11 + off];
    const float* Wv    = (const float*)d_in[12 + off];
    const float* bv    = (const float*)d_in[13 + off];
    const float* Wo    = (const float*)d_in[14 + off];
    const float* bo    = (const float*)d_in[15 + off];
    const float* g1    = (const float*)d_in[16 + off];
    const float* beta1 = (const float*)d_in[17 + off];
    const float* W1    = (const float*)d_in[18 + off];
    const float* b1    = (const float*)d_in[19 + off];
    const float* W2    = (const float*)d_in[20 + off];
    const float* b2    = (const float*)d_in[21 + off];
    const float* g2    = (const float*)d_in[22 + off];
    const float* beta2 = (const float*)d_in[23 + off];
    const float* mW1   = (const float*)d_in[24 + off];
    const float* mb1   = (const float*)d_in[25 + off];
    const float* mW2   = (const float*)d_in[26 + off];
    const float* mb2   = (const float*)d_in[27 + off];

    int E = in_sizes[2] / 2;

    float *ph, *pq, *pk, *pv, *po, *pt1, *pffn;
    cudaGetSymbolAddress((void**)&ph,   g_h);
    cudaGetSymbolAddress((void**)&pq,   g_q);
    cudaGetSymbolAddress((void**)&pk,   g_k);
    cudaGetSymbolAddress((void**)&pv,   g_v);
    cudaGetSymbolAddress((void**)&po,   g_o);
    cudaGetSymbolAddress((void**)&pt1,  g_t1);
    cudaGetSymbolAddress((void**)&pffn, g_ffn);

    // adjacency -> CSR (counts summed for duplicate edges)
    zero_A_kernel<<<(NN * NN + 1023) / 1024, 1024>>>();
    edge_scatter_kernel<<<(E + 255) / 256, 256>>>(ei, E);
    row_count_kernel<<<NN / 8, 256>>>();
    scan_rows_kernel<<<1, 64>>>();
    compact_rows_kernel<<<NN / 8, 256>>>();

    init_h_kernel<<<(NN * DD + 255) / 256, 256>>>(X, pos, projW, projb, peW, peb, ph);

    dim3 g128(DD / 64, NN / 64);       // 2 x 32
    dim3 g256(2 * DD / 64, NN / 64);   // 4 x 32

    for (int l = 0; l < LL; l++) {
        const float* Wql = Wq + l * DD * DD;
        const float* Wkl = Wk + l * DD * DD;
        const float* Wvl = Wv + l * DD * DD;
        const float* Wol = Wo + l * DD * DD;
        sgemm_kernel<<<g128, 256>>>(ph, Wql, bq + l * DD, nullptr, pq, NN, DD, DD, QSCALE, 0);
        sgemm_kernel<<<g128, 256>>>(ph, Wkl, bk + l * DD, nullptr, pk, NN, DD, DD, 1.f, 0);
        sgemm_kernel<<<g128, 256>>>(ph, Wvl, bv + l * DD, nullptr, pv, NN, DD, DD, 1.f, 0);
        vtot_kernel<<<HH, 512>>>(pv);
        attn_kernel<<<(HH * NN + 255) / 256, 256>>>(pq, pk, pv, po);
        sgemm_kernel<<<g128, 256>>>(po, Wol, bo + l * DD, ph, pt1, NN, DD, DD, 1.f, 1);
        bn_kernel<<<DD, 256>>>(pt1, g1 + l * DD, beta1 + l * DD, ph);
        sgemm_kernel<<<g256, 256>>>(ph, W1 + l * DD * 2 * DD, b1 + l * 2 * DD, nullptr,
                                    pffn, NN, 2 * DD, DD, 1.f, 2);
        sgemm_kernel<<<g128, 256>>>(pffn, W2 + l * 2 * DD * DD, b2 + l * DD, ph,
                                    pt1, NN, DD, 2 * DD, 1.f, 1);
        bn_kernel<<<DD, 256>>>(pt1, g2 + l * DD, beta2 + l * DD, ph);
    }

    zero_pooled_kernel<<<(GG * DD + 255) / 256, 256>>>();
    pool_kernel<<<(NN * DD + 255) / 256, 256>>>(gid);
    final_mlp_kernel<<<GG, DD>>>(mW1, mb1, mW2, mb2, (float*)d_out);
}

// round 3
// speedup vs baseline: 1.7695x; 1.7695x over previous
#include <cuda_runtime.h>
#include <math.h>

#define NN   2048
#define DD   128
#define HH   8
#define HDIM 16
#define LL   8
#define GG   16
#define OUTD 64
#define EMAX 65536
#define EPSB 1e-5f
#define QSCALE 0.25f   // HD^-0.5

// ---------------- scratch (device globals; no allocation) ----------------
__device__ int   g_A[NN * NN];
__device__ int   g_nnz[NN];
__device__ int   g_rowptr[NN + 1];
__device__ int   g_cols[EMAX];
__device__ float g_vals[EMAX];
__device__ float g_h  [NN * DD];
__device__ float g_q  [NN * DD];
__device__ float g_k  [NN * DD];
__device__ float g_v  [NN * DD];
__device__ float g_o  [NN * DD];
__device__ float g_t1 [NN * DD];
__device__ float g_ffn[NN * 2 * DD];
__device__ float g_vtot[HH * HDIM];
__device__ float g_pooled[GG * DD];
__device__ float g_bps [32 * DD];   // BN partial sums (32 row-blocks)
__device__ float g_bps2[32 * DD];   // BN partial sums of squares

// ---------------- adjacency build ----------------
__global__ void zero_A_kernel() {
    int t = blockIdx.x * blockDim.x + threadIdx.x;
    if (t < NN * NN / 4) ((int4*)g_A)[t] = make_int4(0, 0, 0, 0);
}

__global__ void edge_scatter_kernel(const int* __restrict__ ei, int E) {
    int e = blockIdx.x * blockDim.x + threadIdx.x;
    if (e >= E) return;
    atomicAdd(&g_A[ei[e] * NN + ei[E + e]], 1);
}

__global__ void row_count_kernel() {
    int warp = (blockIdx.x * blockDim.x + threadIdx.x) >> 5;
    int lane = threadIdx.x & 31;
    if (warp >= NN) return;
    const int4* arow = (const int4*)(g_A + warp * NN);
    int cnt = 0;
    for (int m = lane; m < NN / 4; m += 32) {
        int4 v = arow[m];
        cnt += (v.x != 0) + (v.y != 0) + (v.z != 0) + (v.w != 0);
    }
    #pragma unroll
    for (int o = 16; o > 0; o >>= 1) cnt += __shfl_down_sync(0xffffffffu, cnt, o);
    if (lane == 0) g_nnz[warp] = cnt;
}

__global__ void scan_rows_kernel() {
    __shared__ int chunk[64];
    __shared__ int chunkoff[64];
    int t = threadIdx.x;  // 64 threads
    int s = 0;
    for (int i = 0; i < 32; i++) s += g_nnz[t * 32 + i];
    chunk[t] = s;
    __syncthreads();
    if (t == 0) {
        int run = 0;
        for (int i = 0; i < 64; i++) { chunkoff[i] = run; run += chunk[i]; }
        g_rowptr[NN] = run;
    }
    __syncthreads();
    int off = chunkoff[t];
    for (int i = 0; i < 32; i++) {
        g_rowptr[t * 32 + i] = off;
        off += g_nnz[t * 32 + i];
    }
}

__global__ void compact_rows_kernel() {
    int warp = (blockIdx.x * blockDim.x + threadIdx.x) >> 5;
    int lane = threadIdx.x & 31;
    if (warp >= NN) return;
    int row = warp;
    int pos = g_rowptr[row];
    const int* arow = g_A + row * NN;
    for (int base = 0; base < NN; base += 32) {
        int v = arow[base + lane];
        unsigned mask = __ballot_sync(0xffffffffu, v != 0);
        if (v) {
            int off = __popc(mask & ((1u << lane) - 1));
            g_cols[pos + off] = base + lane;
            g_vals[pos + off] = (float)v;
        }
        pos += __popc(mask);
    }
}

// ---------------- h init ----------------
__global__ void init_h_kernel(const float* __restrict__ X, const float* __restrict__ pos,
                              const float* __restrict__ pW, const float* __restrict__ pb,
                              const float* __restrict__ peW, const float* __restrict__ peb,
                              float* __restrict__ h) {
    int t = blockIdx.x * blockDim.x + threadIdx.x;
    if (t >= NN * DD) return;
    int n = t >> 7, d = t & 127;
    float s = pb[d] + peb[d];
    #pragma unroll
    for (int k = 0; k < 4; k++) s += X[n * 4 + k] * pW[k * DD + d];
    #pragma unroll
    for (int k = 0; k < 2; k++) s += pos[n * 2 + k] * peW[k * DD + d];
    h[t] = s;
}

// ======================= SGEMM (64x64 tile, BK=32, float4) =======================
__device__ __forceinline__ void gemm_tile_64x64(
    const float* __restrict__ A, const float* __restrict__ B,
    int bm, int bn, int K, int ldb, float acc[4][4],
    float (*As)[33], float (*Bs)[64])
{
    int tid = threadIdx.x;
    int ty = tid >> 4, tx = tid & 15;
    int ar  = tid >> 3;          // 0..31
    int ac4 = (tid & 7) * 4;     // 0..28
    int br  = tid >> 4;          // 0..15
    int bc4 = (tid & 15) * 4;    // 0..60
    for (int k0 = 0; k0 < K; k0 += 32) {
        float4 a0 = *(const float4*)&A[(bm + ar) * K + k0 + ac4];
        float4 a1 = *(const float4*)&A[(bm + ar + 32) * K + k0 + ac4];
        As[ar][ac4 + 0] = a0.x; As[ar][ac4 + 1] = a0.y;
        As[ar][ac4 + 2] = a0.z; As[ar][ac4 + 3] = a0.w;
        As[ar + 32][ac4 + 0] = a1.x; As[ar + 32][ac4 + 1] = a1.y;
        As[ar + 32][ac4 + 2] = a1.z; As[ar + 32][ac4 + 3] = a1.w;
        *(float4*)&Bs[br][bc4]      = *(const float4*)&B[(k0 + br) * ldb + bn + bc4];
        *(float4*)&Bs[br + 16][bc4] = *(const float4*)&B[(k0 + br + 16) * ldb + bn + bc4];
        __syncthreads();
        #pragma unroll
        for (int k = 0; k < 32; k++) {
            float4 b4 = *(const float4*)&Bs[k][tx * 4];
            float a0s = As[ty * 4 + 0][k];
            float a1s = As[ty * 4 + 1][k];
            float a2s = As[ty * 4 + 2][k];
            float a3s = As[ty * 4 + 3][k];
            acc[0][0] += a0s * b4.x; acc[0][1] += a0s * b4.y; acc[0][2] += a0s * b4.z; acc[0][3] += a0s * b4.w;
            acc[1][0] += a1s * b4.x; acc[1][1] += a1s * b4.y; acc[1][2] += a1s * b4.z; acc[1][3] += a1s * b4.w;
            acc[2][0] += a2s * b4.x; acc[2][1] += a2s * b4.y; acc[2][2] += a2s * b4.z; acc[2][3] += a2s * b4.w;
            acc[3][0] += a3s * b4.x; acc[3][1] += a3s * b4.y; acc[3][2] += a3s * b4.z; acc[3][3] += a3s * b4.w;
        }
        __syncthreads();
    }
}

// mode 0: C = (AB + bias) * alpha
// mode 1: C = AB + bias + Cadd
// mode 2: C = relu(AB + bias)
__global__ __launch_bounds__(256) void sgemm64(
    const float* __restrict__ A, const float* __restrict__ B,
    const float* __restrict__ bias, const float* __restrict__ Cadd,
    float* __restrict__ C, int N, int K, float alpha, int mode)
{
    __shared__ float As[64][33];
    __shared__ float Bs[32][64];
    int bm = blockIdx.y * 64, bn = blockIdx.x * 64;
    float acc[4][4] = {};
    gemm_tile_64x64(A, B, bm, bn, K, N, acc, As, Bs);

    int ty = threadIdx.x >> 4, tx = threadIdx.x & 15;
    float4 bias4 = *(const float4*)&bias[bn + tx * 4];
    #pragma unroll
    for (int i = 0; i < 4; i++) {
        int m = bm + ty * 4 + i;
        float4 v;
        v.x = acc[i][0] + bias4.x; v.y = acc[i][1] + bias4.y;
        v.z = acc[i][2] + bias4.z; v.w = acc[i][3] + bias4.w;
        if (mode == 0) {
            v.x *= alpha; v.y *= alpha; v.z *= alpha; v.w *= alpha;
        } else if (mode == 1) {
            float4 c4 = *(const float4*)&Cadd[m * N + bn + tx * 4];
            v.x += c4.x; v.y += c4.y; v.z += c4.z; v.w += c4.w;
        } else {
            v.x = fmaxf(v.x, 0.f); v.y = fmaxf(v.y, 0.f);
            v.z = fmaxf(v.z, 0.f); v.w = fmaxf(v.w, 0.f);
        }
        *(float4*)&C[m * N + bn + tx * 4] = v;
    }
}

// Fused QKV: grid (6, 32); segment = blockIdx.x/2 chooses Wq/Wk/Wv.
__global__ __launch_bounds__(256) void qkv_gemm(
    const float* __restrict__ h,
    const float* __restrict__ Wq, const float* __restrict__ Wk, const float* __restrict__ Wv,
    const float* __restrict__ bq, const float* __restrict__ bk, const float* __restrict__ bv,
    float* __restrict__ q, float* __restrict__ k, float* __restrict__ v)
{
    __shared__ float As[64][33];
    __shared__ float Bs[32][64];
    int seg = blockIdx.x >> 1;
    int bn = (blockIdx.x & 1) * 64;
    int bm = blockIdx.y * 64;
    const float* B    = (seg == 0) ? Wq : (seg == 1) ? Wk : Wv;
    const float* bias = (seg == 0) ? bq : (seg == 1) ? bk : bv;
    float* C          = (seg == 0) ? q  : (seg == 1) ? k  : v;
    float alpha       = (seg == 0) ? QSCALE : 1.f;

    float acc[4][4] = {};
    gemm_tile_64x64(h, B, bm, bn, DD, DD, acc, As, Bs);

    int ty = threadIdx.x >> 4, tx = threadIdx.x & 15;
    float4 bias4 = *(const float4*)&bias[bn + tx * 4];
    #pragma unroll
    for (int i = 0; i < 4; i++) {
        int m = bm + ty * 4 + i;
        float4 v4;
        v4.x = (acc[i][0] + bias4.x) * alpha;
        v4.y = (acc[i][1] + bias4.y) * alpha;
        v4.z = (acc[i][2] + bias4.z) * alpha;
        v4.w = (acc[i][3] + bias4.w) * alpha;
        *(float4*)&C[m * DD + bn + tx * 4] = v4;
    }
}

// ---------------- per-head V column sums ----------------
__global__ void vtot_kernel(const float* __restrict__ V) {
    __shared__ float sh[512];
    int head = blockIdx.x;
    int t = threadIdx.x;
    int d = t & 15, g = t >> 4;
    const float* Vh = V + head * (NN * HDIM);
    float part = 0.f;
    for (int row = g; row < NN; row += 32) part += Vh[row * HDIM + d];
    sh[t] = part;
    __syncthreads();
    if (t < HDIM) {
        float s = 0.f;
        for (int gg = 0; gg < 32; gg++) s += sh[gg * HDIM + t];
        g_vtot[head * HDIM + t] = s;
    }
}

// ---------------- sparse multiply-mask softmax attention ----------------
__global__ __launch_bounds__(256) void attn_kernel(
    const float* __restrict__ Q, const float* __restrict__ K,
    const float* __restrict__ V, float* __restrict__ O)
{
    int t = blockIdx.x * blockDim.x + threadIdx.x;
    if (t >= HH * NN) return;
    int head = t >> 11;
    int n = t & (NN - 1);
    const float* Qh = Q + head * (NN * HDIM);
    const float* Kh = K + head * (NN * HDIM);
    const float* Vh = V + head * (NN * HDIM);

    float q[HDIM];
    #pragma unroll
    for (int d = 0; d < HDIM; d++) q[d] = Qh[n * HDIM + d];

    float mrun = 0.f;
    float denom = 0.f;
    float acc[HDIM] = {};
    float vsum[HDIM] = {};

    int s0 = g_rowptr[n], s1 = g_rowptr[n + 1];
    for (int e = s0; e < s1; e++) {
        int m = g_cols[e];
        float a = g_vals[e];
        float dot = 0.f;
        #pragma unroll
        for (int d = 0; d < HDIM; d++) dot += q[d] * Kh[m * HDIM + d];
        float s = dot * a;
        float vreg[HDIM];
        #pragma unroll
        for (int d = 0; d < HDIM; d++) vreg[d] = Vh[m * HDIM + d];
        #pragma unroll
        for (int d = 0; d < HDIM; d++) vsum[d] += vreg[d];
        if (s > mrun) {
            float r = expf(mrun - s);
            denom *= r;
            #pragma unroll
            for (int d = 0; d < HDIM; d++) acc[d] *= r;
            mrun = s;
        }
        float ee = expf(s - mrun);
        denom += ee;
        #pragma unroll
        for (int d = 0; d < HDIM; d++) acc[d] += ee * vreg[d];
    }
    int nnz = s1 - s0;
    float e0 = expf(-mrun);
    denom += (float)(NN - nnz) * e0;
    float inv = 1.f / denom;
    #pragma unroll
    for (int d = 0; d < HDIM; d++)
        O[head * (NN * HDIM) + n * HDIM + d] =
            (acc[d] + e0 * (g_vtot[head * HDIM + d] - vsum[d])) * inv;
}

// ---------------- BatchNorm1d: coalesced two-pass ----------------
__global__ __launch_bounds__(256) void bn_stats_kernel(const float* __restrict__ x) {
    int b = blockIdx.x, t = threadIdx.x;
    int c = t & 127, half = t >> 7;
    float s = 0.f, s2 = 0.f;
    int r0 = b * 64 + half;
    #pragma unroll 8
    for (int i = 0; i < 64; i += 2) {
        float v = x[(r0 + i) * DD + c];
        s += v; s2 += v * v;
    }
    __shared__ float sh[256], sh2[256];
    sh[t] = s; sh2[t] = s2;
    __syncthreads();
    if (half == 0) {
        g_bps [b * DD + c] = sh[c] + sh[c + 128];
        g_bps2[b * DD + c] = sh2[c] + sh2[c + 128];
    }
}

__global__ __launch_bounds__(256) void bn_apply_kernel(
    const float* __restrict__ x, const float* __restrict__ gamma,
    const float* __restrict__ beta, float* __restrict__ out)
{
    __shared__ float scale_s[DD], shift_s[DD];
    int t = threadIdx.x;
    if (t < DD) {
        float s = 0.f, s2 = 0.f;
        #pragma unroll
        for (int b = 0; b < 32; b++) { s += g_bps[b * DD + t]; s2 += g_bps2[b * DD + t]; }
        float m = s * (1.f / NN);
        float var = s2 * (1.f / NN) - m * m;
        float inv = rsqrtf(var + EPSB);
        float gs = gamma[t] * inv;
        scale_s[t] = gs;
        shift_s[t] = beta[t] - gs * m;
    }
    __syncthreads();
    int r0 = blockIdx.x * 16 + (t >> 7);
    int c = t & 127;
    float sc = scale_s[c], sf = shift_s[c];
    #pragma unroll
    for (int i = 0; i < 16; i += 2) {
        int idx = (r0 + i) * DD + c;
        out[idx] = x[idx] * sc + sf;
    }
}

// ---------------- pooling + final MLP ----------------
__global__ void zero_pooled_kernel() {
    int t = blockIdx.x * blockDim.x + threadIdx.x;
    if (t < GG * DD) g_pooled[t] = 0.f;
}

__global__ void pool_kernel(const int* __restrict__ gid) {
    int t = blockIdx.x * blockDim.x + threadIdx.x;
    if (t >= NN * DD) return;
    int n = t >> 7, d = t & 127;
    atomicAdd(&g_pooled[gid[n] * DD + d], g_h[t]);
}

__global__ void final_mlp_kernel(const float* __restrict__ W1, const float* __restrict__ b1,
                                 const float* __restrict__ W2, const float* __restrict__ b2,
                                 float* __restrict__ out) {
    __shared__ float p[DD], hid[DD];
    int g = blockIdx.x, t = threadIdx.x;  // 128 threads
    p[t] = g_pooled[g * DD + t];
    __syncthreads();
    float s = b1[t];
    for (int k = 0; k < DD; k++) s += p[k] * W1[k * DD + t];
    hid[t] = fmaxf(s, 0.f);
    __syncthreads();
    if (t < OUTD) {
        float s2 = b2[t];
        for (int k = 0; k < DD; k++) s2 += hid[k] * W2[k * OUTD + t];
        out[g * OUTD + t] = s2;
    }
}

// ---------------- launch ----------------
extern "C" void kernel_launch(void* const* d_in, const int* in_sizes, int n_in,
                              void* d_out, int out_size) {
    int off = (n_in > 4 && in_sizes[4] == 1) ? 1 : 0;

    const float* X     = (const float*)d_in[0];
    const float* pos   = (const float*)d_in[1];
    const int*   ei    = (const int*)  d_in[2];
    const int*   gid   = (const int*)  d_in[3];
    const float* projW = (const float*)d_in[4 + off];
    const float* projb = (const float*)d_in[5 + off];
    const float* peW   = (const float*)d_in[6 + off];
    const float* peb   = (const float*)d_in[7 + off];
    const float* Wq    = (const float*)d_in[8 + off];
    const float* bq    = (const float*)d_in[9 + off];
    const float* Wk    = (const float*)d_in[10 + off];
    const float* bk    = (const float*)d_in[11 + off];
    const float* Wv    = (const float*)d_in[12 + off];
    const float* bv    = (const float*)d_in[13 + off];
    const float* Wo    = (const float*)d_in[14 + off];
    const float* bo    = (const float*)d_in[15 + off];
    const float* g1    = (const float*)d_in[16 + off];
    const float* beta1 = (const float*)d_in[17 + off];
    const float* W1    = (const float*)d_in[18 + off];
    const float* b1    = (const float*)d_in[19 + off];
    const float* W2    = (const float*)d_in[20 + off];
    const float* b2    = (const float*)d_in[21 + off];
    const float* g2    = (const float*)d_in[22 + off];
    const float* beta2 = (const float*)d_in[23 + off];
    const float* mW1   = (const float*)d_in[24 + off];
    const float* mb1   = (const float*)d_in[25 + off];
    const float* mW2   = (const float*)d_in[26 + off];
    const float* mb2   = (const float*)d_in[27 + off];

    int E = in_sizes[2] / 2;

    float *ph, *pq, *pk, *pv, *po, *pt1, *pffn;
    cudaGetSymbolAddress((void**)&ph,   g_h);
    cudaGetSymbolAddress((void**)&pq,   g_q);
    cudaGetSymbolAddress((void**)&pk,   g_k);
    cudaGetSymbolAddress((void**)&pv,   g_v);
    cudaGetSymbolAddress((void**)&po,   g_o);
    cudaGetSymbolAddress((void**)&pt1,  g_t1);
    cudaGetSymbolAddress((void**)&pffn, g_ffn);

    // adjacency -> CSR
    zero_A_kernel<<<(NN * NN / 4 + 255) / 256, 256>>>();
    edge_scatter_kernel<<<(E + 255) / 256, 256>>>(ei, E);
    row_count_kernel<<<NN / 8, 256>>>();
    scan_rows_kernel<<<1, 64>>>();
    compact_rows_kernel<<<NN / 8, 256>>>();

    init_h_kernel<<<(NN * DD + 255) / 256, 256>>>(X, pos, projW, projb, peW, peb, ph);

    dim3 gQKV(6, NN / 64);
    dim3 g128(DD / 64, NN / 64);
    dim3 g256(2 * DD / 64, NN / 64);

    for (int l = 0; l < LL; l++) {
        qkv_gemm<<<gQKV, 256>>>(ph,
            Wq + l * DD * DD, Wk + l * DD * DD, Wv + l * DD * DD,
            bq + l * DD, bk + l * DD, bv + l * DD, pq, pk, pv);
        vtot_kernel<<<HH, 512>>>(pv);
        attn_kernel<<<(HH * NN + 255) / 256, 256>>>(pq, pk, pv, po);
        sgemm64<<<g128, 256>>>(po, Wo + l * DD * DD, bo + l * DD, ph, pt1, DD, DD, 1.f, 1);
        bn_stats_kernel<<<32, 256>>>(pt1);
        bn_apply_kernel<<<128, 256>>>(pt1, g1 + l * DD, beta1 + l * DD, ph);
        sgemm64<<<g256, 256>>>(ph, W1 + l * DD * 2 * DD, b1 + l * 2 * DD, nullptr,
                               pffn, 2 * DD, DD, 1.f, 2);
        sgemm64<<<g128, 256>>>(pffn, W2 + l * 2 * DD * DD, b2 + l * DD, ph,
                               pt1, DD, 2 * DD, 1.f, 1);
        bn_stats_kernel<<<32, 256>>>(pt1);
        bn_apply_kernel<<<128, 256>>>(pt1, g2 + l * DD, beta2 + l * DD, ph);
    }

    // FIX: zero ALL GG*DD = 2048 pooled floats (round-2 regression: only 256 were
    // zeroed, so graph replays accumulated into stale sums).
    zero_pooled_kernel<<<(GG * DD + 255) / 256, 256>>>();
    pool_kernel<<<(NN * DD + 255) / 256, 256>>>(gid);
    final_mlp_kernel<<<GG, DD>>>(mW1, mb1, mW2, mb2, (float*)d_out);
}

// round 4
// speedup vs baseline: 1.8672x; 1.0552x over previous
#include <cuda_runtime.h>
#include <math.h>

#define NN   2048
#define DD   128
#define HH   8
#define HDIM 16
#define LL   8
#define GG   16
#define OUTD 64
#define EMAX 65536
#define EPSB 1e-5f
#define QSCALE 0.25f   // HD^-0.5

// ---------------- scratch (device globals; no allocation) ----------------
__device__ int   g_A[NN * NN];
__device__ int   g_nnz[NN];
__device__ int   g_rowptr[NN + 1];
__device__ int   g_cols[EMAX];
__device__ float g_vals[EMAX];
__device__ float g_x  [NN * DD];      // layer state (pre-BN2 raw values)
__device__ float g_q  [NN * DD];
__device__ float g_k  [NN * DD];
__device__ float g_v  [NN * DD];
__device__ float g_o  [NN * DD];
__device__ float g_t1 [NN * DD];      // pre-BN1 raw values
__device__ float g_ffn[NN * 2 * DD];
__device__ float g_vtot[HH * HDIM];
__device__ float g_pooled[GG * DD];
// BN stat accumulators + affine vectors
__device__ float g_s1[DD], g_s1q[DD], g_s2[DD], g_s2q[DD];
__device__ float g_sc1[DD], g_sf1[DD], g_sc2[DD], g_sf2[DD];

// ---------------- adjacency build ----------------
__global__ void zero_A_kernel() {
    int t = blockIdx.x * blockDim.x + threadIdx.x;
    if (t < NN * NN / 4) ((int4*)g_A)[t] = make_int4(0, 0, 0, 0);
}

__global__ void edge_scatter_kernel(const int* __restrict__ ei, int E) {
    int e = blockIdx.x * blockDim.x + threadIdx.x;
    if (e >= E) return;
    atomicAdd(&g_A[ei[e] * NN + ei[E + e]], 1);
}

__global__ void row_count_kernel() {
    int warp = (blockIdx.x * blockDim.x + threadIdx.x) >> 5;
    int lane = threadIdx.x & 31;
    if (warp >= NN) return;
    const int4* arow = (const int4*)(g_A + warp * NN);
    int cnt = 0;
    for (int m = lane; m < NN / 4; m += 32) {
        int4 v = arow[m];
        cnt += (v.x != 0) + (v.y != 0) + (v.z != 0) + (v.w != 0);
    }
    #pragma unroll
    for (int o = 16; o > 0; o >>= 1) cnt += __shfl_down_sync(0xffffffffu, cnt, o);
    if (lane == 0) g_nnz[warp] = cnt;
}

__global__ void scan_rows_kernel() {
    __shared__ int chunk[64];
    __shared__ int chunkoff[64];
    int t = threadIdx.x;  // 64 threads
    int s = 0;
    for (int i = 0; i < 32; i++) s += g_nnz[t * 32 + i];
    chunk[t] = s;
    __syncthreads();
    if (t == 0) {
        int run = 0;
        for (int i = 0; i < 64; i++) { chunkoff[i] = run; run += chunk[i]; }
        g_rowptr[NN] = run;
    }
    __syncthreads();
    int off = chunkoff[t];
    for (int i = 0; i < 32; i++) {
        g_rowptr[t * 32 + i] = off;
        off += g_nnz[t * 32 + i];
    }
}

__global__ void compact_rows_kernel() {
    int warp = (blockIdx.x * blockDim.x + threadIdx.x) >> 5;
    int lane = threadIdx.x & 31;
    if (warp >= NN) return;
    int row = warp;
    int pos = g_rowptr[row];
    const int* arow = g_A + row * NN;
    for (int base = 0; base < NN; base += 32) {
        int v = arow[base + lane];
        unsigned mask = __ballot_sync(0xffffffffu, v != 0);
        if (v) {
            int off = __popc(mask & ((1u << lane) - 1));
            g_cols[pos + off] = base + lane;
            g_vals[pos + off] = (float)v;
        }
        pos += __popc(mask);
    }
}

// ---------------- setup: h0 + misc zero/identity ----------------
__global__ void init_h_kernel(const float* __restrict__ X, const float* __restrict__ pos,
                              const float* __restrict__ pW, const float* __restrict__ pb,
                              const float* __restrict__ peW, const float* __restrict__ peb) {
    int t = blockIdx.x * blockDim.x + threadIdx.x;
    if (t >= NN * DD) return;
    int n = t >> 7, d = t & 127;
    float s = pb[d] + peb[d];
    #pragma unroll
    for (int k = 0; k < 4; k++) s += X[n * 4 + k] * pW[k * DD + d];
    #pragma unroll
    for (int k = 0; k < 2; k++) s += pos[n * 2 + k] * peW[k * DD + d];
    g_x[t] = s;
}

__global__ void init_misc_kernel() {
    int t = threadIdx.x;  // 1024
    for (int i = t; i < GG * DD; i += 1024) g_pooled[i] = 0.f;
    if (t < DD) {
        g_sc2[t] = 1.f; g_sf2[t] = 0.f;   // layer-0 "BN2" = identity
        g_s1[t] = 0.f; g_s1q[t] = 0.f;
        g_s2[t] = 0.f; g_s2q[t] = 0.f;
        g_vtot[t] = 0.f;                  // HH*HDIM == 128
    }
}

// ======================= GEMM core (64x64 tile, BK=32, float4) =======================
// Optional per-column affine on A-load: a = a*scA[col]+sfA[col] (col = K index).
template<bool AFF>
__device__ __forceinline__ void gemm_tile_64x64(
    const float* __restrict__ A, const float* __restrict__ B,
    int bm, int bn, int K, int ldb,
    const float* __restrict__ scA, const float* __restrict__ sfA,
    float acc[4][4], float (*As)[33], float (*Bs)[64])
{
    int tid = threadIdx.x;
    int ty = tid >> 4, tx = tid & 15;
    int ar  = tid >> 3;          // 0..31
    int ac4 = (tid & 7) * 4;     // 0..28
    int br  = tid >> 4;          // 0..15
    int bc4 = (tid & 15) * 4;    // 0..60
    for (int k0 = 0; k0 < K; k0 += 32) {
        float4 a0 = *(const float4*)&A[(bm + ar) * K + k0 + ac4];
        float4 a1 = *(const float4*)&A[(bm + ar + 32) * K + k0 + ac4];
        if (AFF) {
            float4 sc = *(const float4*)&scA[k0 + ac4];
            float4 sf = *(const float4*)&sfA[k0 + ac4];
            a0.x = a0.x * sc.x + sf.x; a0.y = a0.y * sc.y + sf.y;
            a0.z = a0.z * sc.z + sf.z; a0.w = a0.w * sc.w + sf.w;
            a1.x = a1.x * sc.x + sf.x; a1.y = a1.y * sc.y + sf.y;
            a1.z = a1.z * sc.z + sf.z; a1.w = a1.w * sc.w + sf.w;
        }
        As[ar][ac4 + 0] = a0.x; As[ar][ac4 + 1] = a0.y;
        As[ar][ac4 + 2] = a0.z; As[ar][ac4 + 3] = a0.w;
        As[ar + 32][ac4 + 0] = a1.x; As[ar + 32][ac4 + 1] = a1.y;
        As[ar + 32][ac4 + 2] = a1.z; As[ar + 32][ac4 + 3] = a1.w;
        *(float4*)&Bs[br][bc4]      = *(const float4*)&B[(k0 + br) * ldb + bn + bc4];
        *(float4*)&Bs[br + 16][bc4] = *(const float4*)&B[(k0 + br + 16) * ldb + bn + bc4];
        __syncthreads();
        #pragma unroll
        for (int k = 0; k < 32; k++) {
            float4 b4 = *(const float4*)&Bs[k][tx * 4];
            float a0s = As[ty * 4 + 0][k];
            float a1s = As[ty * 4 + 1][k];
            float a2s = As[ty * 4 + 2][k];
            float a3s = As[ty * 4 + 3][k];
            acc[0][0] += a0s * b4.x; acc[0][1] += a0s * b4.y; acc[0][2] += a0s * b4.z; acc[0][3] += a0s * b4.w;
            acc[1][0] += a1s * b4.x; acc[1][1] += a1s * b4.y; acc[1][2] += a1s * b4.z; acc[1][3] += a1s * b4.w;
            acc[2][0] += a2s * b4.x; acc[2][1] += a2s * b4.y; acc[2][2] += a2s * b4.z; acc[2][3] += a2s * b4.w;
            acc[3][0] += a3s * b4.x; acc[3][1] += a3s * b4.y; acc[3][2] += a3s * b4.z; acc[3][3] += a3s * b4.w;
        }
        __syncthreads();
    }
}

// Column reduction of per-thread partials (4 cols each) -> 64 column sums in red[],
// then thread t<64 owns column t. red must hold 16*64 floats.
__device__ __forceinline__ void colreduce64(float* red, const float ps[4], float out[1], int tid) {
    int ty = tid >> 4, tx = tid & 15;
    __syncthreads();
    #pragma unroll
    for (int j = 0; j < 4; j++) red[ty * 64 + tx * 4 + j] = ps[j];
    __syncthreads();
    if (tid < 64) {
        float s = 0.f;
        #pragma unroll
        for (int r = 0; r < 16; r++) s += red[r * 64 + tid];
        out[0] = s;
    }
}

// ---------------- QKV fused GEMM (A-load applies BN2 affine of prev layer) ----------------
// grid (6, 32); seg = blockIdx.x>>1; V-segment blocks also accumulate g_vtot.
__global__ __launch_bounds__(256) void qkv_gemm(
    const float* __restrict__ Wq, const float* __restrict__ Wk, const float* __restrict__ Wv,
    const float* __restrict__ bq, const float* __restrict__ bk, const float* __restrict__ bv)
{
    __shared__ float As[64][33];
    __shared__ float Bs[32][64];
    int seg = blockIdx.x >> 1;
    int bn = (blockIdx.x & 1) * 64;
    int bm = blockIdx.y * 64;
    const float* B    = (seg == 0) ? Wq : (seg == 1) ? Wk : Wv;
    const float* bias = (seg == 0) ? bq : (seg == 1) ? bk : bv;
    float* C          = (seg == 0) ? g_q : (seg == 1) ? g_k : g_v;
    float alpha       = (seg == 0) ? QSCALE : 1.f;

    float acc[4][4] = {};
    gemm_tile_64x64<true>(g_x, B, bm, bn, DD, DD, g_sc2, g_sf2, acc, As, Bs);

    int tid = threadIdx.x;
    int ty = tid >> 4, tx = tid & 15;
    float4 bias4 = *(const float4*)&bias[bn + tx * 4];
    float ps[4] = {};
    #pragma unroll
    for (int i = 0; i < 4; i++) {
        int m = bm + ty * 4 + i;
        float4 v4;
        v4.x = (acc[i][0] + bias4.x) * alpha;
        v4.y = (acc[i][1] + bias4.y) * alpha;
        v4.z = (acc[i][2] + bias4.z) * alpha;
        v4.w = (acc[i][3] + bias4.w) * alpha;
        ps[0] += v4.x; ps[1] += v4.y; ps[2] += v4.z; ps[3] += v4.w;
        *(float4*)&C[m * DD + bn + tx * 4] = v4;
    }
    if (seg == 2) {   // block-uniform branch: fold V column sums into g_vtot
        float cs[1];
        colreduce64(&As[0][0], ps, cs, tid);
        if (tid < 64) {
            int head = bm >> 8;                 // 256 rows per head chunk
            int d = (bn + tid) & 15;            // flat-index mod 16 = head dim
            atomicAdd(&g_vtot[head * HDIM + d], cs[0]);
        }
    }
}

// ---------------- Wo GEMM: out = o@Wo + bo + BN2affine(x_prev); accumulate BN1 stats ----------------
__global__ __launch_bounds__(256) void gemm_wo(
    const float* __restrict__ Wo, const float* __restrict__ bo)
{
    __shared__ float As[64][33];
    __shared__ float Bs[32][64];
    int bm = blockIdx.y * 64, bn = blockIdx.x * 64;
    float acc[4][4] = {};
    gemm_tile_64x64<false>(g_o, Wo, bm, bn, DD, DD, nullptr, nullptr, acc, As, Bs);

    int tid = threadIdx.x;
    int ty = tid >> 4, tx = tid & 15;
    float4 bias4 = *(const float4*)&bo[bn + tx * 4];
    float4 sc4 = *(const float4*)&g_sc2[bn + tx * 4];
    float4 sf4 = *(const float4*)&g_sf2[bn + tx * 4];
    float ps[4] = {}, ps2[4] = {};
    #pragma unroll
    for (int i = 0; i < 4; i++) {
        int m = bm + ty * 4 + i;
        float4 x4 = *(const float4*)&g_x[m * DD + bn + tx * 4];
        float4 v4;
        v4.x = acc[i][0] + bias4.x + x4.x * sc4.x + sf4.x;
        v4.y = acc[i][1] + bias4.y + x4.y * sc4.y + sf4.y;
        v4.z = acc[i][2] + bias4.z + x4.z * sc4.z + sf4.z;
        v4.w = acc[i][3] + bias4.w + x4.w * sc4.w + sf4.w;
        ps[0] += v4.x; ps[1] += v4.y; ps[2] += v4.z; ps[3] += v4.w;
        ps2[0] += v4.x * v4.x; ps2[1] += v4.y * v4.y;
        ps2[2] += v4.z * v4.z; ps2[3] += v4.w * v4.w;
        *(float4*)&g_t1[m * DD + bn + tx * 4] = v4;
    }
    float cs[1];
    colreduce64(&As[0][0], ps, cs, tid);
    if (tid < 64) atomicAdd(&g_s1[bn + tid], cs[0]);
    colreduce64(&As[0][0], ps2, cs, tid);
    if (tid < 64) atomicAdd(&g_s1q[bn + tid], cs[0]);
}

// ---------------- FFN1: relu(BN1affine(t1) @ W1 + b1) -> g_ffn ----------------
__global__ __launch_bounds__(256) void gemm_ffn1(
    const float* __restrict__ W1, const float* __restrict__ b1)
{
    __shared__ float As[64][33];
    __shared__ float Bs[32][64];
    int bm = blockIdx.y * 64, bn = blockIdx.x * 64;
    float acc[4][4] = {};
    gemm_tile_64x64<true>(g_t1, W1, bm, bn, DD, 2 * DD, g_sc1, g_sf1, acc, As, Bs);

    int ty = threadIdx.x >> 4, tx = threadIdx.x & 15;
    float4 bias4 = *(const float4*)&b1[bn + tx * 4];
    #pragma unroll
    for (int i = 0; i < 4; i++) {
        int m = bm + ty * 4 + i;
        float4 v4;
        v4.x = fmaxf(acc[i][0] + bias4.x, 0.f);
        v4.y = fmaxf(acc[i][1] + bias4.y, 0.f);
        v4.z = fmaxf(acc[i][2] + bias4.z, 0.f);
        v4.w = fmaxf(acc[i][3] + bias4.w, 0.f);
        *(float4*)&g_ffn[m * 2 * DD + bn + tx * 4] = v4;
    }
}

// ---------------- FFN2: g_x = ffn@W2 + b2 + BN1affine(t1); accumulate BN2 stats ----------------
__global__ __launch_bounds__(256) void gemm_ffn2(
    const float* __restrict__ W2, const float* __restrict__ b2)
{
    __shared__ float As[64][33];
    __shared__ float Bs[32][64];
    int bm = blockIdx.y * 64, bn = blockIdx.x * 64;
    float acc[4][4] = {};
    gemm_tile_64x64<false>(g_ffn, W2, bm, bn, 2 * DD, DD, nullptr, nullptr, acc, As, Bs);

    int tid = threadIdx.x;
    int ty = tid >> 4, tx = tid & 15;
    float4 bias4 = *(const float4*)&b2[bn + tx * 4];
    float4 sc4 = *(const float4*)&g_sc1[bn + tx * 4];
    float4 sf4 = *(const float4*)&g_sf1[bn + tx * 4];
    float ps[4] = {}, ps2[4] = {};
    #pragma unroll
    for (int i = 0; i < 4; i++) {
        int m = bm + ty * 4 + i;
        float4 t4 = *(const float4*)&g_t1[m * DD + bn + tx * 4];
        float4 v4;
        v4.x = acc[i][0] + bias4.x + t4.x * sc4.x + sf4.x;
        v4.y = acc[i][1] + bias4.y + t4.y * sc4.y + sf4.y;
        v4.z = acc[i][2] + bias4.z + t4.z * sc4.z + sf4.z;
        v4.w = acc[i][3] + bias4.w + t4.w * sc4.w + sf4.w;
        ps[0] += v4.x; ps[1] += v4.y; ps[2] += v4.z; ps[3] += v4.w;
        ps2[0] += v4.x * v4.x; ps2[1] += v4.y * v4.y;
        ps2[2] += v4.z * v4.z; ps2[3] += v4.w * v4.w;
        *(float4*)&g_x[m * DD + bn + tx * 4] = v4;   // in-place layer state update
    }
    float cs[1];
    colreduce64(&As[0][0], ps, cs, tid);
    if (tid < 64) atomicAdd(&g_s2[bn + tid], cs[0]);
    colreduce64(&As[0][0], ps2, cs, tid);
    if (tid < 64) atomicAdd(&g_s2q[bn + tid], cs[0]);
}

// ---------------- BN finalize: stats -> affine, reset stats ----------------
__global__ void bn_finalize_kernel(float* __restrict__ S, float* __restrict__ Sq,
                                   const float* __restrict__ gamma, const float* __restrict__ beta,
                                   float* __restrict__ sc, float* __restrict__ sf,
                                   int zero_vtot)
{
    int c = threadIdx.x;  // 128
    float s = S[c], q = Sq[c];
    float m = s * (1.f / NN);
    float var = q * (1.f / NN) - m * m;
    float inv = rsqrtf(var + EPSB);
    float gs = gamma[c] * inv;
    sc[c] = gs;
    sf[c] = beta[c] - gs * m;
    S[c] = 0.f; Sq[c] = 0.f;
    if (zero_vtot) g_vtot[c] = 0.f;
}

// ---------------- sparse multiply-mask softmax attention ----------------
__global__ __launch_bounds__(256) void attn_kernel()
{
    int t = blockIdx.x * blockDim.x + threadIdx.x;
    if (t >= HH * NN) return;
    int head = t >> 11;
    int n = t & (NN - 1);
    const float* Qh = g_q + head * (NN * HDIM);
    const float* Kh = g_k + head * (NN * HDIM);
    const float* Vh = g_v + head * (NN * HDIM);

    float q[HDIM];
    #pragma unroll
    for (int d = 0; d < HDIM; d++) q[d] = Qh[n * HDIM + d];

    float mrun = 0.f;
    float denom = 0.f;
    float acc[HDIM] = {};
    float vsum[HDIM] = {};

    int s0 = g_rowptr[n], s1 = g_rowptr[n + 1];
    for (int e = s0; e < s1; e++) {
        int m = g_cols[e];
        float a = g_vals[e];
        float dot = 0.f;
        #pragma unroll
        for (int d = 0; d < HDIM; d++) dot += q[d] * Kh[m * HDIM + d];
        float s = dot * a;
        float vreg[HDIM];
        #pragma unroll
        for (int d = 0; d < HDIM; d++) vreg[d] = Vh[m * HDIM + d];
        #pragma unroll
        for (int d = 0; d < HDIM; d++) vsum[d] += vreg[d];
        if (s > mrun) {
            float r = expf(mrun - s);
            denom *= r;
            #pragma unroll
            for (int d = 0; d < HDIM; d++) acc[d] *= r;
            mrun = s;
        }
        float ee = expf(s - mrun);
        denom += ee;
        #pragma unroll
        for (int d = 0; d < HDIM; d++) acc[d] += ee * vreg[d];
    }
    int nnz = s1 - s0;
    float e0 = expf(-mrun);
    denom += (float)(NN - nnz) * e0;
    float inv = 1.f / denom;
    #pragma unroll
    for (int d = 0; d < HDIM; d++)
        g_o[head * (NN * HDIM) + n * HDIM + d] =
            (acc[d] + e0 * (g_vtot[head * HDIM + d] - vsum[d])) * inv;
}

// ---------------- pooling (applies final BN2 affine) + final MLP ----------------
__global__ void pool_kernel(const int* __restrict__ gid) {
    int t = blockIdx.x * blockDim.x + threadIdx.x;
    if (t >= NN * DD) return;
    int n = t >> 7, d = t & 127;
    float v = g_x[t] * g_sc2[d] + g_sf2[d];
    atomicAdd(&g_pooled[gid[n] * DD + d], v);
}

__global__ void final_mlp_kernel(const float* __restrict__ W1, const float* __restrict__ b1,
                                 const float* __restrict__ W2, const float* __restrict__ b2,
                                 float* __restrict__ out) {
    __shared__ float p[DD], hid[DD];
    int g = blockIdx.x, t = threadIdx.x;  // 128 threads
    p[t] = g_pooled[g * DD + t];
    __syncthreads();
    float s = b1[t];
    for (int k = 0; k < DD; k++) s += p[k] * W1[k * DD + t];
    hid[t] = fmaxf(s, 0.f);
    __syncthreads();
    if (t < OUTD) {
        float s2 = b2[t];
        for (int k = 0; k < DD; k++) s2 += hid[k] * W2[k * OUTD + t];
        out[g * OUTD + t] = s2;
    }
}

// ---------------- launch ----------------
extern "C" void kernel_launch(void* const* d_in, const int* in_sizes, int n_in,
                              void* d_out, int out_size) {
    int off = (n_in > 4 && in_sizes[4] == 1) ? 1 : 0;

    const float* X     = (const float*)d_in[0];
    const float* pos   = (const float*)d_in[1];
    const int*   ei    = (const int*)  d_in[2];
    const int*   gid   = (const int*)  d_in[3];
    const float* projW = (const float*)d_in[4 + off];
    const float* projb = (const float*)d_in[5 + off];
    const float* peW   = (const float*)d_in[6 + off];
    const float* peb   = (const float*)d_in[7 + off];
    const float* Wq    = (const float*)d_in[8 + off];
    const float* bq    = (const float*)d_in[9 + off];
    const float* Wk    = (const float*)d_in[10 + off];
    const float* bk    = (const float*)d_in[11 + off];
    const float* Wv    = (const float*)d_in[12 + off];
    const float* bv    = (const float*)d_in[13 + off];
    const float* Wo    = (const float*)d_in[14 + off];
    const float* bo    = (const float*)d_in[15 + off];
    const float* g1    = (const float*)d_in[16 + off];
    const float* beta1 = (const float*)d_in[17 + off];
    const float* W1    = (const float*)d_in[18 + off];
    const float* b1    = (const float*)d_in[19 + off];
    const float* W2    = (const float*)d_in[20 + off];
    const float* b2    = (const float*)d_in[21 + off];
    const float* g2    = (const float*)d_in[22 + off];
    const float* beta2 = (const float*)d_in[23 + off];
    const float* mW1   = (const float*)d_in[24 + off];
    const float* mb1   = (const float*)d_in[25 + off];
    const float* mW2   = (const float*)d_in[26 + off];
    const float* mb2   = (const float*)d_in[27 + off];

    int E = in_sizes[2] / 2;

    float *pS1, *pS1q, *pS2, *pS2q, *pSc1, *pSf1, *pSc2, *pSf2;
    cudaGetSymbolAddress((void**)&pS1,  g_s1);
    cudaGetSymbolAddress((void**)&pS1q, g_s1q);
    cudaGetSymbolAddress((void**)&pS2,  g_s2);
    cudaGetSymbolAddress((void**)&pS2q, g_s2q);
    cudaGetSymbolAddress((void**)&pSc1, g_sc1);
    cudaGetSymbolAddress((void**)&pSf1, g_sf1);
    cudaGetSymbolAddress((void**)&pSc2, g_sc2);
    cudaGetSymbolAddress((void**)&pSf2, g_sf2);

    // adjacency -> CSR
    zero_A_kernel<<<(NN * NN / 4 + 255) / 256, 256>>>();
    edge_scatter_kernel<<<(E + 255) / 256, 256>>>(ei, E);
    row_count_kernel<<<NN / 8, 256>>>();
    scan_rows_kernel<<<1, 64>>>();
    compact_rows_kernel<<<NN / 8, 256>>>();

    init_h_kernel<<<(NN * DD + 255) / 256, 256>>>(X, pos, projW, projb, peW, peb);
    init_misc_kernel<<<1, 1024>>>();

    dim3 gQKV(6, NN / 64);
    dim3 g128(DD / 64, NN / 64);        // (2, 32)
    dim3 g256(2 * DD / 64, NN / 64);    // (4, 32)

    for (int l = 0; l < LL; l++) {
        qkv_gemm<<<gQKV, 256>>>(
            Wq + l * DD * DD, Wk + l * DD * DD, Wv + l * DD * DD,
            bq + l * DD, bk + l * DD, bv + l * DD);
        attn_kernel<<<(HH * NN + 255) / 256, 256>>>();
        gemm_wo<<<g128, 256>>>(Wo + l * DD * DD, bo + l * DD);
        bn_finalize_kernel<<<1, DD>>>(pS1, pS1q, g1 + l * DD, beta1 + l * DD, pSc1, pSf1, 0);
        gemm_ffn1<<<g256, 256>>>(W1 + l * DD * 2 * DD, b1 + l * 2 * DD);
        gemm_ffn2<<<g128, 256>>>(W2 + l * 2 * DD * DD, b2 + l * DD);
        bn_finalize_kernel<<<1, DD>>>(pS2, pS2q, g2 + l * DD, beta2 + l * DD, pSc2, pSf2, 1);
    }

    pool_kernel<<<(NN * DD + 255) / 256, 256>>>(gid);
    final_mlp_kernel<<<GG, DD>>>(mW1, mb1, mW2, mb2, (float*)d_out);
}

// round 5
// speedup vs baseline: 4.0431x; 2.1654x over previous
#include <cuda_runtime.h>
#include <math.h>

#define NN   2048
#define DD   128
#define HH   8
#define HDIM 16
#define LL   8
#define GG   16
#define OUTD 64
#define EMAX 65536
#define EPSB 1e-5f
#define QSCALE 0.25f   // HD^-0.5

// ---------------- scratch (device globals; no allocation) ----------------
__device__ int   g_A[NN * NN];
__device__ int   g_nnz[NN];
__device__ int   g_rowptr[NN + 1];
__device__ int   g_cols[EMAX];
__device__ __align__(16) float g_vals[EMAX];
__device__ __align__(16) float g_x  [NN * DD];      // layer state (pre-BN2 raw values)
__device__ __align__(16) float g_q  [NN * DD];      // PERMUTED: [n][h*16+d]
__device__ __align__(16) float g_k  [NN * DD];      // PERMUTED
__device__ __align__(16) float g_v  [NN * DD];      // PERMUTED
__device__ __align__(16) float g_o  [NN * DD];      // flat [r][c] (GEMM layout)
__device__ __align__(16) float g_t1 [NN * DD];      // pre-BN1 raw values
__device__ __align__(16) float g_ffn[NN * 2 * DD];
__device__ __align__(16) float g_vtot[HH * HDIM];
__device__ __align__(16) float g_pooled[GG * DD];
// BN stat accumulators + affine vectors
__device__ __align__(16) float g_s1[DD], g_s1q[DD], g_s2[DD], g_s2q[DD];
__device__ __align__(16) float g_sc1[DD], g_sf1[DD], g_sc2[DD], g_sf2[DD];

// ---------------- adjacency build ----------------
__global__ void zero_A_kernel() {
    int t = blockIdx.x * blockDim.x + threadIdx.x;
    if (t < NN * NN / 4) ((int4*)g_A)[t] = make_int4(0, 0, 0, 0);
}

__global__ void edge_scatter_kernel(const int* __restrict__ ei, int E) {
    int e = blockIdx.x * blockDim.x + threadIdx.x;
    if (e >= E) return;
    atomicAdd(&g_A[ei[e] * NN + ei[E + e]], 1);
}

__global__ void row_count_kernel() {
    int warp = (blockIdx.x * blockDim.x + threadIdx.x) >> 5;
    int lane = threadIdx.x & 31;
    if (warp >= NN) return;
    const int4* arow = (const int4*)(g_A + warp * NN);
    int cnt = 0;
    for (int m = lane; m < NN / 4; m += 32) {
        int4 v = arow[m];
        cnt += (v.x != 0) + (v.y != 0) + (v.z != 0) + (v.w != 0);
    }
    #pragma unroll
    for (int o = 16; o > 0; o >>= 1) cnt += __shfl_down_sync(0xffffffffu, cnt, o);
    if (lane == 0) g_nnz[warp] = cnt;
}

__global__ void scan_rows_kernel() {
    __shared__ int chunk[64];
    __shared__ int chunkoff[64];
    int t = threadIdx.x;  // 64 threads
    int s = 0;
    for (int i = 0; i < 32; i++) s += g_nnz[t * 32 + i];
    chunk[t] = s;
    __syncthreads();
    if (t == 0) {
        int run = 0;
        for (int i = 0; i < 64; i++) { chunkoff[i] = run; run += chunk[i]; }
        g_rowptr[NN] = run;
    }
    __syncthreads();
    int off = chunkoff[t];
    for (int i = 0; i < 32; i++) {
        g_rowptr[t * 32 + i] = off;
        off += g_nnz[t * 32 + i];
    }
}

__global__ void compact_rows_kernel() {
    int warp = (blockIdx.x * blockDim.x + threadIdx.x) >> 5;
    int lane = threadIdx.x & 31;
    if (warp >= NN) return;
    int row = warp;
    int pos = g_rowptr[row];
    const int* arow = g_A + row * NN;
    for (int base = 0; base < NN; base += 32) {
        int v = arow[base + lane];
        unsigned mask = __ballot_sync(0xffffffffu, v != 0);
        if (v) {
            int off = __popc(mask & ((1u << lane) - 1));
            g_cols[pos + off] = base + lane;
            g_vals[pos + off] = (float)v;
        }
        pos += __popc(mask);
    }
}

// ---------------- setup: h0 + misc zero/identity ----------------
__global__ void init_h_kernel(const float* __restrict__ X, const float* __restrict__ pos,
                              const float* __restrict__ pW, const float* __restrict__ pb,
                              const float* __restrict__ peW, const float* __restrict__ peb) {
    int t = blockIdx.x * blockDim.x + threadIdx.x;
    if (t >= NN * DD) return;
    int n = t >> 7, d = t & 127;
    float s = pb[d] + peb[d];
    #pragma unroll
    for (int k = 0; k < 4; k++) s += X[n * 4 + k] * pW[k * DD + d];
    #pragma unroll
    for (int k = 0; k < 2; k++) s += pos[n * 2 + k] * peW[k * DD + d];
    g_x[t] = s;
}

__global__ void init_misc_kernel() {
    int t = threadIdx.x;  // 1024
    for (int i = t; i < GG * DD; i += 1024) g_pooled[i] = 0.f;
    if (t < DD) {
        g_sc2[t] = 1.f; g_sf2[t] = 0.f;   // layer-0 "BN2" = identity
        g_s1[t] = 0.f; g_s1q[t] = 0.f;
        g_s2[t] = 0.f; g_s2q[t] = 0.f;
        g_vtot[t] = 0.f;                  // HH*HDIM == 128
    }
}

// ======================= GEMM core (64x64 tile, BK=32, float4) =======================
// Optional per-column affine on A-load: a = a*scA[col]+sfA[col] (col = K index).
template<bool AFF>
__device__ __forceinline__ void gemm_tile_64x64(
    const float* __restrict__ A, const float* __restrict__ B,
    int bm, int bn, int K, int ldb,
    const float* __restrict__ scA, const float* __restrict__ sfA,
    float acc[4][4], float (*As)[33], float (*Bs)[64])
{
    int tid = threadIdx.x;
    int ty = tid >> 4, tx = tid & 15;
    int ar  = tid >> 3;          // 0..31
    int ac4 = (tid & 7) * 4;     // 0..28
    int br  = tid >> 4;          // 0..15
    int bc4 = (tid & 15) * 4;    // 0..60
    for (int k0 = 0; k0 < K; k0 += 32) {
        float4 a0 = *(const float4*)&A[(bm + ar) * K + k0 + ac4];
        float4 a1 = *(const float4*)&A[(bm + ar + 32) * K + k0 + ac4];
        if (AFF) {
            float4 sc = *(const float4*)&scA[k0 + ac4];
            float4 sf = *(const float4*)&sfA[k0 + ac4];
            a0.x = a0.x * sc.x + sf.x; a0.y = a0.y * sc.y + sf.y;
            a0.z = a0.z * sc.z + sf.z; a0.w = a0.w * sc.w + sf.w;
            a1.x = a1.x * sc.x + sf.x; a1.y = a1.y * sc.y + sf.y;
            a1.z = a1.z * sc.z + sf.z; a1.w = a1.w * sc.w + sf.w;
        }
        As[ar][ac4 + 0] = a0.x; As[ar][ac4 + 1] = a0.y;
        As[ar][ac4 + 2] = a0.z; As[ar][ac4 + 3] = a0.w;
        As[ar + 32][ac4 + 0] = a1.x; As[ar + 32][ac4 + 1] = a1.y;
        As[ar + 32][ac4 + 2] = a1.z; As[ar + 32][ac4 + 3] = a1.w;
        *(float4*)&Bs[br][bc4]      = *(const float4*)&B[(k0 + br) * ldb + bn + bc4];
        *(float4*)&Bs[br + 16][bc4] = *(const float4*)&B[(k0 + br + 16) * ldb + bn + bc4];
        __syncthreads();
        #pragma unroll
        for (int k = 0; k < 32; k++) {
            float4 b4 = *(const float4*)&Bs[k][tx * 4];
            float a0s = As[ty * 4 + 0][k];
            float a1s = As[ty * 4 + 1][k];
            float a2s = As[ty * 4 + 2][k];
            float a3s = As[ty * 4 + 3][k];
            acc[0][0] += a0s * b4.x; acc[0][1] += a0s * b4.y; acc[0][2] += a0s * b4.z; acc[0][3] += a0s * b4.w;
            acc[1][0] += a1s * b4.x; acc[1][1] += a1s * b4.y; acc[1][2] += a1s * b4.z; acc[1][3] += a1s * b4.w;
            acc[2][0] += a2s * b4.x; acc[2][1] += a2s * b4.y; acc[2][2] += a2s * b4.z; acc[2][3] += a2s * b4.w;
            acc[3][0] += a3s * b4.x; acc[3][1] += a3s * b4.y; acc[3][2] += a3s * b4.z; acc[3][3] += a3s * b4.w;
        }
        __syncthreads();
    }
}

// Column reduction of per-thread partials (4 cols each) -> thread t<64 owns column t.
__device__ __forceinline__ void colreduce64(float* red, const float ps[4], float out[1], int tid) {
    int ty = tid >> 4, tx = tid & 15;
    __syncthreads();
    #pragma unroll
    for (int j = 0; j < 4; j++) red[ty * 64 + tx * 4 + j] = ps[j];
    __syncthreads();
    if (tid < 64) {
        float s = 0.f;
        #pragma unroll
        for (int r = 0; r < 16; r++) s += red[r * 64 + tid];
        out[0] = s;
    }
}

// ---------------- QKV fused GEMM (A-load applies BN2 affine of prev layer) ----------------
// grid (6, 32); seg = blockIdx.x>>1; writes PERMUTED layout [n][h*16+d].
// V-segment blocks also accumulate g_vtot.
__global__ __launch_bounds__(256) void qkv_gemm(
    const float* __restrict__ Wq, const float* __restrict__ Wk, const float* __restrict__ Wv,
    const float* __restrict__ bq, const float* __restrict__ bk, const float* __restrict__ bv)
{
    __shared__ float As[64][33];
    __shared__ float Bs[32][64];
    int seg = blockIdx.x >> 1;
    int bn = (blockIdx.x & 1) * 64;
    int bm = blockIdx.y * 64;
    const float* B    = (seg == 0) ? Wq : (seg == 1) ? Wk : Wv;
    const float* bias = (seg == 0) ? bq : (seg == 1) ? bk : bv;
    float* C          = (seg == 0) ? g_q : (seg == 1) ? g_k : g_v;
    float alpha       = (seg == 0) ? QSCALE : 1.f;

    float acc[4][4] = {};
    gemm_tile_64x64<true>(g_x, B, bm, bn, DD, DD, g_sc2, g_sf2, acc, As, Bs);

    int tid = threadIdx.x;
    int ty = tid >> 4, tx = tid & 15;
    float4 bias4 = *(const float4*)&bias[bn + tx * 4];
    float ps[4] = {};
    int c = bn + tx * 4;
    int h = bm >> 8;                       // head constant within 64-row tile
    #pragma unroll
    for (int i = 0; i < 4; i++) {
        int r = bm + ty * 4 + i;
        float4 v4;
        v4.x = (acc[i][0] + bias4.x) * alpha;
        v4.y = (acc[i][1] + bias4.y) * alpha;
        v4.z = (acc[i][2] + bias4.z) * alpha;
        v4.w = (acc[i][3] + bias4.w) * alpha;
        ps[0] += v4.x; ps[1] += v4.y; ps[2] += v4.z; ps[3] += v4.w;
        // perm: node n = (r%256)*8 + c/16, offset n*128 + h*16 + c%16
        int n = ((r & 255) << 3) + (c >> 4);
        *(float4*)&C[n * DD + (h << 4) + (c & 15)] = v4;
    }
    if (seg == 2) {   // block-uniform branch: fold V column sums into g_vtot
        float cs[1];
        colreduce64(&As[0][0], ps, cs, tid);
        if (tid < 64) {
            int d = (bn + tid) & 15;            // flat-col mod 16 = head dim
            atomicAdd(&g_vtot[h * HDIM + d], cs[0]);
        }
    }
}

// ---------------- Wo GEMM: out = o@Wo + bo + BN2affine(x_prev); accumulate BN1 stats ----------------
__global__ __launch_bounds__(256) void gemm_wo(
    const float* __restrict__ Wo, const float* __restrict__ bo)
{
    __shared__ float As[64][33];
    __shared__ float Bs[32][64];
    int bm = blockIdx.y * 64, bn = blockIdx.x * 64;
    float acc[4][4] = {};
    gemm_tile_64x64<false>(g_o, Wo, bm, bn, DD, DD, nullptr, nullptr, acc, As, Bs);

    int tid = threadIdx.x;
    int ty = tid >> 4, tx = tid & 15;
    float4 bias4 = *(const float4*)&bo[bn + tx * 4];
    float4 sc4 = *(const float4*)&g_sc2[bn + tx * 4];
    float4 sf4 = *(const float4*)&g_sf2[bn + tx * 4];
    float ps[4] = {}, ps2[4] = {};
    #pragma unroll
    for (int i = 0; i < 4; i++) {
        int m = bm + ty * 4 + i;
        float4 x4 = *(const float4*)&g_x[m * DD + bn + tx * 4];
        float4 v4;
        v4.x = acc[i][0] + bias4.x + x4.x * sc4.x + sf4.x;
        v4.y = acc[i][1] + bias4.y + x4.y * sc4.y + sf4.y;
        v4.z = acc[i][2] + bias4.z + x4.z * sc4.z + sf4.z;
        v4.w = acc[i][3] + bias4.w + x4.w * sc4.w + sf4.w;
        ps[0] += v4.x; ps[1] += v4.y; ps[2] += v4.z; ps[3] += v4.w;
        ps2[0] += v4.x * v4.x; ps2[1] += v4.y * v4.y;
        ps2[2] += v4.z * v4.z; ps2[3] += v4.w * v4.w;
        *(float4*)&g_t1[m * DD + bn + tx * 4] = v4;
    }
    float cs[1];
    colreduce64(&As[0][0], ps, cs, tid);
    if (tid < 64) atomicAdd(&g_s1[bn + tid], cs[0]);
    colreduce64(&As[0][0], ps2, cs, tid);
    if (tid < 64) atomicAdd(&g_s1q[bn + tid], cs[0]);
}

// ---------------- FFN1: relu(BN1affine(t1) @ W1 + b1) -> g_ffn ----------------
__global__ __launch_bounds__(256) void gemm_ffn1(
    const float* __restrict__ W1, const float* __restrict__ b1)
{
    __shared__ float As[64][33];
    __shared__ float Bs[32][64];
    int bm = blockIdx.y * 64, bn = blockIdx.x * 64;
    float acc[4][4] = {};
    gemm_tile_64x64<true>(g_t1, W1, bm, bn, DD, 2 * DD, g_sc1, g_sf1, acc, As, Bs);

    int ty = threadIdx.x >> 4, tx = threadIdx.x & 15;
    float4 bias4 = *(const float4*)&b1[bn + tx * 4];
    #pragma unroll
    for (int i = 0; i < 4; i++) {
        int m = bm + ty * 4 + i;
        float4 v4;
        v4.x = fmaxf(acc[i][0] + bias4.x, 0.f);
        v4.y = fmaxf(acc[i][1] + bias4.y, 0.f);
        v4.z = fmaxf(acc[i][2] + bias4.z, 0.f);
        v4.w = fmaxf(acc[i][3] + bias4.w, 0.f);
        *(float4*)&g_ffn[m * 2 * DD + bn + tx * 4] = v4;
    }
}

// ---------------- FFN2: g_x = ffn@W2 + b2 + BN1affine(t1); accumulate BN2 stats ----------------
__global__ __launch_bounds__(256) void gemm_ffn2(
    const float* __restrict__ W2, const float* __restrict__ b2)
{
    __shared__ float As[64][33];
    __shared__ float Bs[32][64];
    int bm = blockIdx.y * 64, bn = blockIdx.x * 64;
    float acc[4][4] = {};
    gemm_tile_64x64<false>(g_ffn, W2, bm, bn, 2 * DD, DD, nullptr, nullptr, acc, As, Bs);

    int tid = threadIdx.x;
    int ty = tid >> 4, tx = tid & 15;
    float4 bias4 = *(const float4*)&b2[bn + tx * 4];
    float4 sc4 = *(const float4*)&g_sc1[bn + tx * 4];
    float4 sf4 = *(const float4*)&g_sf1[bn + tx * 4];
    float ps[4] = {}, ps2[4] = {};
    #pragma unroll
    for (int i = 0; i < 4; i++) {
        int m = bm + ty * 4 + i;
        float4 t4 = *(const float4*)&g_t1[m * DD + bn + tx * 4];
        float4 v4;
        v4.x = acc[i][0] + bias4.x + t4.x * sc4.x + sf4.x;
        v4.y = acc[i][1] + bias4.y + t4.y * sc4.y + sf4.y;
        v4.z = acc[i][2] + bias4.z + t4.z * sc4.z + sf4.z;
        v4.w = acc[i][3] + bias4.w + t4.w * sc4.w + sf4.w;
        ps[0] += v4.x; ps[1] += v4.y; ps[2] += v4.z; ps[3] += v4.w;
        ps2[0] += v4.x * v4.x; ps2[1] += v4.y * v4.y;
        ps2[2] += v4.z * v4.z; ps2[3] += v4.w * v4.w;
        *(float4*)&g_x[m * DD + bn + tx * 4] = v4;   // in-place layer state update
    }
    float cs[1];
    colreduce64(&As[0][0], ps, cs, tid);
    if (tid < 64) atomicAdd(&g_s2[bn + tid], cs[0]);
    colreduce64(&As[0][0], ps2, cs, tid);
    if (tid < 64) atomicAdd(&g_s2q[bn + tid], cs[0]);
}

// ---------------- BN finalize: stats -> affine, reset stats ----------------
__global__ void bn_finalize_kernel(float* __restrict__ S, float* __restrict__ Sq,
                                   const float* __restrict__ gamma, const float* __restrict__ beta,
                                   float* __restrict__ sc, float* __restrict__ sf,
                                   int zero_vtot)
{
    int c = threadIdx.x;  // 128
    float s = S[c], q = Sq[c];
    float m = s * (1.f / NN);
    float var = q * (1.f / NN) - m * m;
    float inv = rsqrtf(var + EPSB);
    float gs = gamma[c] * inv;
    sc[c] = gs;
    sf[c] = beta[c] - gs * m;
    S[c] = 0.f; Sq[c] = 0.f;
    if (zero_vtot) g_vtot[c] = 0.f;
}

// ---------------- attention: warp per node, 4-lane group per head ----------------
// Q/K/V in PERMUTED layout [n][h*16+d]; output written FLAT for the Wo GEMM.
__global__ __launch_bounds__(256) void attn_kernel()
{
    int n = (blockIdx.x * blockDim.x + threadIdx.x) >> 5;   // node = warp id
    if (n >= NN) return;
    int lane = threadIdx.x & 31;
    int ld = lane & 3;

    const float4* __restrict__ qp = (const float4*)g_q;
    const float4* __restrict__ kp = (const float4*)g_k;
    const float4* __restrict__ vp = (const float4*)g_v;
    const int*    __restrict__ cols = g_cols;
    const float*  __restrict__ vals = g_vals;

    float4 q4 = qp[n * (DD / 4) + lane];

    float mrun = 0.f, denom = 0.f;
    float4 acc = make_float4(0.f, 0.f, 0.f, 0.f);
    float4 vs  = make_float4(0.f, 0.f, 0.f, 0.f);

    int s0 = g_rowptr[n], s1 = g_rowptr[n + 1];
    for (int e = s0; e < s1; e++) {
        int m = cols[e];
        float a = vals[e];
        float4 k4 = kp[m * (DD / 4) + lane];
        float4 v4 = vp[m * (DD / 4) + lane];
        float dot = q4.x * k4.x + q4.y * k4.y + q4.z * k4.z + q4.w * k4.w;
        dot += __shfl_xor_sync(0xffffffffu, dot, 1);
        dot += __shfl_xor_sync(0xffffffffu, dot, 2);   // full 16-dim dot per 4-lane group
        float s = dot * a;
        vs.x += v4.x; vs.y += v4.y; vs.z += v4.z; vs.w += v4.w;
        if (s > mrun) {
            float r = expf(mrun - s);
            denom *= r;
            acc.x *= r; acc.y *= r; acc.z *= r; acc.w *= r;
            mrun = s;
        }
        float ee = expf(s - mrun);
        denom += ee;
        acc.x += ee * v4.x; acc.y += ee * v4.y;
        acc.z += ee * v4.z; acc.w += ee * v4.w;
    }
    int nnz = s1 - s0;
    float e0 = expf(-mrun);
    denom += (float)(NN - nnz) * e0;
    float inv = 1.f / denom;
    float4 vt = *(const float4*)&g_vtot[lane * 4];   // vtot[h*16+d] == vtot[lane*4]
    float4 o;
    o.x = (acc.x + e0 * (vt.x - vs.x)) * inv;
    o.y = (acc.y + e0 * (vt.y - vs.y)) * inv;
    o.z = (acc.z + e0 * (vt.z - vs.z)) * inv;
    o.w = (acc.w + e0 * (vt.w - vs.w)) * inv;
    // flat write: r = h*256 + n/8, c = (n%8)*16 + ld*4
    int h = lane >> 2;
    int r = (h << 8) + (n >> 3);
    int c = ((n & 7) << 4) + (ld << 2);
    *(float4*)&g_o[r * DD + c] = o;
}

// ---------------- pooling (applies final BN2 affine) + final MLP ----------------
__global__ void pool_kernel(const int* __restrict__ gid) {
    int t = blockIdx.x * blockDim.x + threadIdx.x;
    if (t >= NN * DD) return;
    int n = t >> 7, d = t & 127;
    float v = g_x[t] * g_sc2[d] + g_sf2[d];
    atomicAdd(&g_pooled[gid[n] * DD + d], v);
}

__global__ void final_mlp_kernel(const float* __restrict__ W1, const float* __restrict__ b1,
                                 const float* __restrict__ W2, const float* __restrict__ b2,
                                 float* __restrict__ out) {
    __shared__ float p[DD], hid[DD];
    int g = blockIdx.x, t = threadIdx.x;  // 128 threads
    p[t] = g_pooled[g * DD + t];
    __syncthreads();
    float s = b1[t];
    for (int k = 0; k < DD; k++) s += p[k] * W1[k * DD + t];
    hid[t] = fmaxf(s, 0.f);
    __syncthreads();
    if (t < OUTD) {
        float s2 = b2[t];
        for (int k = 0; k < DD; k++) s2 += hid[k] * W2[k * OUTD + t];
        out[g * OUTD + t] = s2;
    }
}

// ---------------- launch ----------------
extern "C" void kernel_launch(void* const* d_in, const int* in_sizes, int n_in,
                              void* d_out, int out_size) {
    int off = (n_in > 4 && in_sizes[4] == 1) ? 1 : 0;

    const float* X     = (const float*)d_in[0];
    const float* pos   = (const float*)d_in[1];
    const int*   ei    = (const int*)  d_in[2];
    const int*   gid   = (const int*)  d_in[3];
    const float* projW = (const float*)d_in[4 + off];
    const float* projb = (const float*)d_in[5 + off];
    const float* peW   = (const float*)d_in[6 + off];
    const float* peb   = (const float*)d_in[7 + off];
    const float* Wq    = (const float*)d_in[8 + off];
    const float* bq    = (const float*)d_in[9 + off];
    const float* Wk    = (const float*)d_in[10 + off];
    const float* bk    = (const float*)d_in[11 + off];
    const float* Wv    = (const float*)d_in[12 + off];
    const float* bv    = (const float*)d_in[13 + off];
    const float* Wo    = (const float*)d_in[14 + off];
    const float* bo    = (const float*)d_in[15 + off];
    const float* g1    = (const float*)d_in[16 + off];
    const float* beta1 = (const float*)d_in[17 + off];
    const float* W1    = (const float*)d_in[18 + off];
    const float* b1    = (const float*)d_in[19 + off];
    const float* W2    = (const float*)d_in[20 + off];
    const float* b2    = (const float*)d_in[21 + off];
    const float* g2    = (const float*)d_in[22 + off];
    const float* beta2 = (const float*)d_in[23 + off];
    const float* mW1   = (const float*)d_in[24 + off];
    const float* mb1   = (const float*)d_in[25 + off];
    const float* mW2   = (const float*)d_in[26 + off];
    const float* mb2   = (const float*)d_in[27 + off];

    int E = in_sizes[2] / 2;

    float *pS1, *pS1q, *pS2, *pS2q, *pSc1, *pSf1, *pSc2, *pSf2;
    cudaGetSymbolAddress((void**)&pS1,  g_s1);
    cudaGetSymbolAddress((void**)&pS1q, g_s1q);
    cudaGetSymbolAddress((void**)&pS2,  g_s2);
    cudaGetSymbolAddress((void**)&pS2q, g_s2q);
    cudaGetSymbolAddress((void**)&pSc1, g_sc1);
    cudaGetSymbolAddress((void**)&pSf1, g_sf1);
    cudaGetSymbolAddress((void**)&pSc2, g_sc2);
    cudaGetSymbolAddress((void**)&pSf2, g_sf2);

    // adjacency -> CSR
    zero_A_kernel<<<(NN * NN / 4 + 255) / 256, 256>>>();
    edge_scatter_kernel<<<(E + 255) / 256, 256>>>(ei, E);
    row_count_kernel<<<NN / 8, 256>>>();
    scan_rows_kernel<<<1, 64>>>();
    compact_rows_kernel<<<NN / 8, 256>>>();

    init_h_kernel<<<(NN * DD + 255) / 256, 256>>>(X, pos, projW, projb, peW, peb);
    init_misc_kernel<<<1, 1024>>>();

    dim3 gQKV(6, NN / 64);
    dim3 g128(DD / 64, NN / 64);        // (2, 32)
    dim3 g256(2 * DD / 64, NN / 64);    // (4, 32)

    for (int l = 0; l < LL; l++) {
        qkv_gemm<<<gQKV, 256>>>(
            Wq + l * DD * DD, Wk + l * DD * DD, Wv + l * DD * DD,
            bq + l * DD, bk + l * DD, bv + l * DD);
        attn_kernel<<<NN * 32 / 256, 256>>>();
        gemm_wo<<<g128, 256>>>(Wo + l * DD * DD, bo + l * DD);
        bn_finalize_kernel<<<1, DD>>>(pS1, pS1q, g1 + l * DD, beta1 + l * DD, pSc1, pSf1, 0);
        gemm_ffn1<<<g256, 256>>>(W1 + l * DD * 2 * DD, b1 + l * 2 * DD);
        gemm_ffn2<<<g128, 256>>>(W2 + l * 2 * DD * DD, b2 + l * DD);
        bn_finalize_kernel<<<1, DD>>>(pS2, pS2q, g2 + l * DD, beta2 + l * DD, pSc2, pSf2, 1);
    }

    pool_kernel<<<(NN * DD + 255) / 256, 256>>>(gid);
    final_mlp_kernel<<<GG, DD>>>(mW1, mb1, mW2, mb2, (float*)d_out);
}